// round 16
// baseline (speedup 1.0000x reference)
#include <cuda_runtime.h>
#include <cstdint>

// SoftProposal on this operator reduces exactly to out = feature * (1/196):
//
//   D_ is symmetric; D = D_ / rowsum(D_) is row-stochastic (rows sum to 1).
//   M0 = ones/S  =>  D @ M0 = (1/S) * D @ ones = (1/S) * ones = M0.
//   The uniform vector is an exact fixed point of the diffusion iteration, so
//   the reference's first scan step produces newM == M0 (up to fp32 rounding
//   ~1e-9), err ~ 0 < 1e-4 sets done=True, and M stays ones/S for all 10
//   steps. Final output = M.reshape(B,1,n,n) * feature = feature / 196.
//
// Pure 205.6 MB stream; ILP-8 far-stride for MLP depth, streaming cache hints.

#define BB 128
#define KK 1024
#define SS 196
#define TOT4 (BB * KK * (SS / 4))   // 6,422,528 float4
#define OCT  (TOT4 / 8)             // 802,816 = 3136 * 256  (exact)
#define INV_S (1.0f / 196.0f)

__global__ void __launch_bounds__(256) scale_kernel(const float4* __restrict__ f,
                                                    float4* __restrict__ out) {
    int idx = blockIdx.x * 256 + threadIdx.x;   // 0 .. OCT-1, exact cover

    const float4* p = f + idx;
    float4 x0 = __ldcs(p);
    float4 x1 = __ldcs(p + OCT);
    float4 x2 = __ldcs(p + 2 * OCT);
    float4 x3 = __ldcs(p + 3 * OCT);
    float4 x4 = __ldcs(p + 4 * OCT);
    float4 x5 = __ldcs(p + 5 * OCT);
    float4 x6 = __ldcs(p + 6 * OCT);
    float4 x7 = __ldcs(p + 7 * OCT);

    x0.x *= INV_S; x0.y *= INV_S; x0.z *= INV_S; x0.w *= INV_S;
    x1.x *= INV_S; x1.y *= INV_S; x1.z *= INV_S; x1.w *= INV_S;
    x2.x *= INV_S; x2.y *= INV_S; x2.z *= INV_S; x2.w *= INV_S;
    x3.x *= INV_S; x3.y *= INV_S; x3.z *= INV_S; x3.w *= INV_S;
    x4.x *= INV_S; x4.y *= INV_S; x4.z *= INV_S; x4.w *= INV_S;
    x5.x *= INV_S; x5.y *= INV_S; x5.z *= INV_S; x5.w *= INV_S;
    x6.x *= INV_S; x6.y *= INV_S; x6.z *= INV_S; x6.w *= INV_S;
    x7.x *= INV_S; x7.y *= INV_S; x7.z *= INV_S; x7.w *= INV_S;

    float4* q = out + idx;
    __stcs(q,           x0);
    __stcs(q + OCT,     x1);
    __stcs(q + 2 * OCT, x2);
    __stcs(q + 3 * OCT, x3);
    __stcs(q + 4 * OCT, x4);
    __stcs(q + 5 * OCT, x5);
    __stcs(q + 6 * OCT, x6);
    __stcs(q + 7 * OCT, x7);
}

extern "C" void kernel_launch(void* const* d_in, const int* in_sizes, int n_in,
                              void* d_out, int out_size) {
    const float4* f = (const float4*)d_in[0];
    float4* out = (float4*)d_out;
    scale_kernel<<<OCT / 256, 256>>>(f, out);
}

// round 17
// speedup vs baseline: 1.0009x; 1.0009x over previous
#include <cuda_runtime.h>
#include <cstdint>

// SoftProposal on this operator reduces exactly to out = feature * (1/196):
//
//   D_ is symmetric; D = D_ / rowsum(D_) is row-stochastic (rows sum to 1).
//   M0 = ones/S  =>  D @ M0 = (1/S) * D @ ones = (1/S) * ones = M0.
//   The uniform vector is an exact fixed point of the diffusion iteration, so
//   the reference's first scan step produces newM == M0 (up to fp32 rounding
//   ~1e-9), err ~ 0 < 1e-4 sets done=True, and M stays ones/S for all 10
//   steps. Final output = M.reshape(B,1,n,n) * feature = feature / 196.
//
// Pure 205.6 MB stream at the measured HBM ceiling (~5.3 TB/s ncu-effective;
// confirmed by 4 independent variants all landing 28.4-29.1 us). ILP-4
// far-stride gives full MLP coverage at 78% occupancy; ILP-8 regressed via
// register pressure. This is the converged form.

#define BB 128
#define KK 1024
#define SS 196
#define TOT4 (BB * KK * (SS / 4))   // 6,422,528 float4
#define QTR  (TOT4 / 4)             // 1,605,632 = 6272 * 256  (exact)
#define INV_S (1.0f / 196.0f)

__global__ void __launch_bounds__(256) scale_kernel(const float4* __restrict__ f,
                                                    float4* __restrict__ out) {
    int idx = blockIdx.x * 256 + threadIdx.x;   // 0 .. QTR-1, exact cover

    const float4* p0 = f + idx;
    float4 x0 = __ldcs(p0);
    float4 x1 = __ldcs(p0 + QTR);
    float4 x2 = __ldcs(p0 + 2 * QTR);
    float4 x3 = __ldcs(p0 + 3 * QTR);

    x0.x *= INV_S; x0.y *= INV_S; x0.z *= INV_S; x0.w *= INV_S;
    x1.x *= INV_S; x1.y *= INV_S; x1.z *= INV_S; x1.w *= INV_S;
    x2.x *= INV_S; x2.y *= INV_S; x2.z *= INV_S; x2.w *= INV_S;
    x3.x *= INV_S; x3.y *= INV_S; x3.z *= INV_S; x3.w *= INV_S;

    float4* q0 = out + idx;
    __stcs(q0,           x0);
    __stcs(q0 + QTR,     x1);
    __stcs(q0 + 2 * QTR, x2);
    __stcs(q0 + 3 * QTR, x3);
}

extern "C" void kernel_launch(void* const* d_in, const int* in_sizes, int n_in,
                              void* d_out, int out_size) {
    const float4* f = (const float4*)d_in[0];
    float4* out = (float4*)d_out;
    scale_kernel<<<QTR / 256, 256>>>(f, out);
}